// round 11
// baseline (speedup 1.0000x reference)
#include <cuda_runtime.h>
#include <math.h>

// ---------------------------------------------------------------------------
// DE3 fused: 256-bin histogram entropy, single kernel.
//   out = B * (8 + sum_i p_i log2 p_i),  p_i = counts[i] / (2048*2048)
//
// Rule extracted from R1-R10: ptxas's prefetch pipeline survives ONLY at its
// preferred ~97 regs; ANY tight __launch_bounds__ min-blocks cap makes it
// fully serialize the loads (R3/R5/R6/R10: 1.0-1.4 TB/s). So: do NOT cap
// registers. Instead let occupancy come from the smaller histogram:
//   packed-u8 counters, 4 per u32 word, word-sized RMW only:
//     word(warp, lane, row) at index  warp*2048 + row*32 + lane, row=bin>>2
//     increment = 1 << ((bin&3)*8)        (bank == lane: conflict-free)
//   256 B/thread -> 32 KB/block; at ptxas's 97 regs the REGISTER limit gives
//   floor(65536/(97*128)) = 5 blocks/SM = 20 warps/SM (R7 had 12).
// In-flight loads: 20 warps x ~8 LDG.128 x 512 B ~= 82 KB/SM (R7: 49 KB).
//
// Grid 2220: <= 60 float4/thread -> max 240 hits per u8 counter < 256. Safe.
// Loop body = byte-identical to R7's proven pipeline; only the BUMP differs.
// Reduction: dp4a byte-lane sums (proven R3/R10 layout); fused finalize.
// ---------------------------------------------------------------------------

#define NUM_BINS 256
#define THREADS  128
#define BLOCKS   2220
#define SMEM_BYTES 32768      // 4 warps * 64 rows * 128 B
#define DEPTH    12

__device__ unsigned int g_counts[NUM_BINS];   // zero-initialized at load
__device__ unsigned int g_done;

__global__ void __launch_bounds__(THREADS)    // NO min-blocks hint: regs free
de3_fused(const float4* __restrict__ in4, int n4,
          const float* __restrict__ in, int n,
          float* __restrict__ out)
{
    extern __shared__ unsigned char smem[];
    unsigned* __restrict__ hw = reinterpret_cast<unsigned*>(smem);

    // zero private histograms: 2048 uint4 / 128 threads = 16 STS.128 each
    {
        uint4* z = reinterpret_cast<uint4*>(smem);
        #pragma unroll
        for (int i = threadIdx.x; i < SMEM_BYTES / 16; i += THREADS)
            z[i] = make_uint4(0u, 0u, 0u, 0u);
    }
    __syncthreads();

    const unsigned lane = threadIdx.x & 31u;
    const unsigned warp = threadIdx.x >> 5;
    // word index of (warp, lane, row 0):  warp*2048 + lane
    const unsigned wbase = (warp << 11) + lane;

    // bump: word-sized smem RMW only, bank == lane (conflict-free any bins)
    #define DE3_BUMP(V) do {                                           \
        unsigned b_  = __float2uint_rz(fminf((V), 255.0f));            \
        unsigned w_  = wbase + ((b_ >> 2) << 5);                       \
        unsigned inc_ = 1u << ((b_ & 3u) << 3);                        \
        hw[w_] += inc_;                                                \
    } while (0)
    #define DE3_BUMP4(Q) do { DE3_BUMP((Q).x); DE3_BUMP((Q).y);       \
                              DE3_BUMP((Q).z); DE3_BUMP((Q).w); } while (0)

    const int S  = BLOCKS * THREADS;     // 284160
    const int SD = DEPTH * S;
    int i = blockIdx.x * THREADS + threadIdx.x;

    // ---- DEPTH-deep software pipeline: R7's exact proven shape ------------
    if (i + (DEPTH - 1) * S < n4) {
        float4 buf[DEPTH];
        #pragma unroll
        for (int k = 0; k < DEPTH; ++k) buf[k] = __ldcs(in4 + i + k * S);
        i += SD;
        while (i + (DEPTH - 1) * S < n4) {
            float4 nxt[DEPTH];
            #pragma unroll
            for (int k = 0; k < DEPTH; ++k) nxt[k] = __ldcs(in4 + i + k * S);
            #pragma unroll
            for (int k = 0; k < DEPTH; ++k) DE3_BUMP4(buf[k]);
            #pragma unroll
            for (int k = 0; k < DEPTH; ++k) buf[k] = nxt[k];
            i += SD;
        }
        #pragma unroll
        for (int k = 0; k < DEPTH; ++k) DE3_BUMP4(buf[k]);
    }
    for (; i < n4; i += S) {
        float4 a = __ldcs(in4 + i);
        DE3_BUMP4(a);
    }
    if (blockIdx.x == 0 && (int)threadIdx.x < (n & 3)) {
        float v = in[(n & ~3) + (int)threadIdx.x];
        DE3_BUMP(v);
    }
    #undef DE3_BUMP4
    #undef DE3_BUMP
    __syncthreads();

    // ---- block reduction (proven dp4a byte-lane sums) ---------------------
    // Word (warp w, row r, lane l) at word-index w*2048 + r*32 + l holds the
    // u8 counters of bins 4r..4r+3 for thread (w,l).
    // Thread j: row r = j&63, warps {wp0, wp0+1}, wp0 = (j>>6)*2.
    {
        const unsigned j = threadIdx.x;
        const unsigned r = j & 63u;
        const unsigned wp0 = (j >> 6) << 1;
        unsigned s0 = 0u, s1 = 0u, s2 = 0u, s3 = 0u;
        #pragma unroll
        for (unsigned w = 0; w < 2; ++w) {
            const unsigned rowbase = (wp0 + w) * 2048u + r * 32u;
            #pragma unroll
            for (unsigned k = 0; k < 32; ++k) {
                unsigned l = (k + j) & 31u;
                unsigned wd = hw[rowbase + l];
                s0 = __dp4a(wd, 0x00000001u, s0);
                s1 = __dp4a(wd, 0x00000100u, s1);
                s2 = __dp4a(wd, 0x00010000u, s2);
                s3 = __dp4a(wd, 0x01000000u, s3);
            }
        }
        atomicAdd(&g_counts[4u * r + 0u], s0);
        atomicAdd(&g_counts[4u * r + 1u], s1);
        atomicAdd(&g_counts[4u * r + 2u], s2);
        atomicAdd(&g_counts[4u * r + 3u], s3);
    }

    // ---- last-block finalize ----------------------------------------------
    __threadfence();
    __shared__ unsigned ticket;
    if (threadIdx.x == 0) ticket = atomicAdd(&g_done, 1u);
    __syncthreads();

    if (ticket == gridDim.x - 1) {
        const unsigned j = threadIdx.x;
        const float inv_temp = 1.0f / 4194304.0f;     // 1/(2048*2048)
        unsigned c0 = __ldcg(&g_counts[j]);
        unsigned c1 = __ldcg(&g_counts[j + 128]);
        double term = 0.0;
        if (c0) { float p = (float)c0 * inv_temp; term += (double)(p * log2f(p)); }
        if (c1) { float p = (float)c1 * inv_temp; term += (double)(p * log2f(p)); }

        #pragma unroll
        for (int o = 16; o > 0; o >>= 1)
            term += __shfl_down_sync(0xffffffffu, term, o);

        __shared__ double sred[4];
        if ((j & 31u) == 0u) sred[j >> 5] = term;
        __syncthreads();
        if (j == 0) {
            double s = sred[0] + sred[1] + sred[2] + sred[3];
            float B = (float)(n >> 22);               // n / (2048*2048)
            out[0] = (float)((double)B * (8.0 + s));
        }
        __syncthreads();
        // reset globals for the next graph replay
        g_counts[j] = 0u;
        g_counts[j + 128] = 0u;
        if (j == 0) g_done = 0u;
    }
}

extern "C" void kernel_launch(void* const* d_in, const int* in_sizes, int n_in,
                              void* d_out, int out_size) {
    const float* img = (const float*)d_in[0];
    int n = in_sizes[0];
    cudaFuncSetAttribute(de3_fused,
                         cudaFuncAttributeMaxDynamicSharedMemorySize, SMEM_BYTES);
    cudaFuncSetAttribute(de3_fused,
                         cudaFuncAttributePreferredSharedMemoryCarveout, 100);
    de3_fused<<<BLOCKS, THREADS, SMEM_BYTES>>>(
        (const float4*)img, n >> 2, img, n, (float*)d_out);
}

// round 12
// speedup vs baseline: 3.3907x; 3.3907x over previous
#include <cuda_runtime.h>
#include <math.h>

// ---------------------------------------------------------------------------
// DE3 fused: 256-bin histogram entropy, single kernel, TMA-staged.
//   out = B * (8 + sum_i p_i log2 p_i),  p_i = counts[i] / (2048*2048)
//
// R1-R11 verdict: LDG+register prefetch is capped at ~8 loads/warp by ptxas
// (any deviation from the one blessed loop shape serializes it). So move MLP
// into the TMA engine: cp.async.bulk (1D, mbarrier complete_tx) streams
// 16 KB chunks into a 3-deep smem ring — zero registers, zero scoreboard
// window, compiler-proof.
//
// Layout per block (128 thr):
//   [0,64K)    per-thread u16 histograms, R7's proven layout:
//                counter(thread,bin) @ warp*16384 + bin*64 + lane*2
//   [64K,112K) stage ring: 3 x 16 KB (1024 float4)
//   [112K,+24) 3 mbarriers
// 296 blocks (2/SM). 16384 chunks; <=56/block -> <=1792 elems/thread
// (u16 safe; packed reduction carry-free: 32*1792 < 65536).
// ---------------------------------------------------------------------------

#define NUM_BINS 256
#define THREADS  128
#define BLOCKS   296
#define HISTO_BYTES 65536
#define NBUF      3
#define CHUNK_F4  1024
#define CHUNK_BYTES 16384
#define STAGE_OFF  HISTO_BYTES
#define MBAR_OFF  (HISTO_BYTES + NBUF * CHUNK_BYTES)     // 114688
#define SMEM_BYTES (MBAR_OFF + 32)                       // 114720

__device__ unsigned int g_counts[NUM_BINS];   // zero-init at load
__device__ unsigned int g_done;

__device__ __forceinline__ void mbar_init(unsigned addr, unsigned cnt) {
    asm volatile("mbarrier.init.shared.b64 [%0], %1;" :: "r"(addr), "r"(cnt) : "memory");
}
__device__ __forceinline__ void mbar_expect_tx(unsigned addr, unsigned bytes) {
    asm volatile("mbarrier.arrive.expect_tx.shared.b64 _, [%0], %1;"
                 :: "r"(addr), "r"(bytes) : "memory");
}
__device__ __forceinline__ void mbar_wait(unsigned addr, unsigned parity) {
    unsigned done;
    asm volatile(
        "{\n\t.reg .pred p;\n\t"
        "mbarrier.try_wait.parity.acquire.cta.shared::cta.b64 p, [%1], %2;\n\t"
        "selp.b32 %0, 1, 0, p;\n\t}"
        : "=r"(done) : "r"(addr), "r"(parity) : "memory");
    if (!done) {
        asm volatile(
            "{\n\t.reg .pred P1;\n\t"
            "W_%=:\n\t"
            "mbarrier.try_wait.parity.acquire.cta.shared::cta.b64 P1, [%0], %1, 0x989680;\n\t"
            "@P1 bra.uni D_%=;\n\t"
            "bra.uni W_%=;\n\t"
            "D_%=:\n\t}"
            :: "r"(addr), "r"(parity) : "memory");
    }
}
__device__ __forceinline__ void tma_1d(unsigned dst, const void* src,
                                       unsigned bytes, unsigned mbar) {
    asm volatile(
        "cp.async.bulk.shared::cluster.global.mbarrier::complete_tx::bytes "
        "[%0], [%1], %2, [%3];"
        :: "r"(dst), "l"(src), "r"(bytes), "r"(mbar) : "memory");
}
__device__ __forceinline__ void fence_proxy() {
    asm volatile("fence.proxy.async.shared::cta;" ::: "memory");
}

__global__ void __launch_bounds__(THREADS)
de3_fused(const float4* __restrict__ in4, int n4,
          const float* __restrict__ in, int n,
          float* __restrict__ out)
{
    extern __shared__ unsigned char smem[];
    unsigned smem_u32;
    asm("{ .reg .u64 t; cvta.to.shared.u64 t, %1; cvt.u32.u64 %0, t; }"
        : "=r"(smem_u32) : "l"(smem));
    const unsigned stage_u32 = smem_u32 + STAGE_OFF;
    const unsigned mbar_u32  = smem_u32 + MBAR_OFF;

    const unsigned t    = threadIdx.x;
    const unsigned lane = t & 31u;
    const unsigned warp = t >> 5;
    const unsigned lanebase = (warp << 14) + (lane << 1);  // warp*16KB + lane*2

    // zero private histograms
    {
        uint4* z = reinterpret_cast<uint4*>(smem);
        #pragma unroll
        for (int i = t; i < HISTO_BYTES / 16; i += THREADS)
            z[i] = make_uint4(0u, 0u, 0u, 0u);
    }
    if (t == 0) {
        #pragma unroll
        for (int s = 0; s < NBUF; ++s) mbar_init(mbar_u32 + 8u * s, 1u);
        fence_proxy();
    }
    __syncthreads();

    const int G       = gridDim.x;
    const int nchunks = n4 >> 10;                 // 1024 float4 per chunk

    // ---- prologue: launch NBUF chunk copies immediately --------------------
    if (t == 0) {
        #pragma unroll
        for (int s = 0; s < NBUF; ++s) {
            int c = blockIdx.x + s * G;
            if (c < nchunks) {
                mbar_expect_tx(mbar_u32 + 8u * s, CHUNK_BYTES);
                tma_1d(stage_u32 + (unsigned)s * CHUNK_BYTES,
                       in4 + (size_t)c * CHUNK_F4, CHUNK_BYTES, mbar_u32 + 8u * s);
            }
        }
    }

    // R7's proven u16 bump (1 IMAD address)
    #define DE3_BUMP(V) do {                                                  \
        unsigned b_ = __float2uint_rz(fminf((V), 255.0f));                    \
        unsigned short* c_ =                                                  \
            reinterpret_cast<unsigned short*>(smem + (b_ * 64u + lanebase));  \
        *c_ = (unsigned short)(*c_ + 1u);                                     \
    } while (0)
    #define DE3_BUMP4(Q) do { DE3_BUMP((Q).x); DE3_BUMP((Q).y);              \
                              DE3_BUMP((Q).z); DE3_BUMP((Q).w); } while (0)

    // ---- main loop: consume ring, refill 3 ahead --------------------------
    const float4* stage_f4 = reinterpret_cast<const float4*>(smem + STAGE_OFF);
    int c = blockIdx.x, local_i = 0;
    while (c < nchunks) {
        int buf = local_i - (local_i / NBUF) * NBUF;          // local_i % 3
        unsigned parity = (unsigned)(local_i / NBUF) & 1u;
        mbar_wait(mbar_u32 + 8u * buf, parity);

        const float4* slot = stage_f4 + buf * CHUNK_F4 + t;
        #pragma unroll
        for (int k = 0; k < CHUNK_F4 / THREADS; ++k) {        // 8 LDS.128
            float4 v = slot[k * THREADS];
            DE3_BUMP4(v);
        }
        __syncthreads();                   // everyone done with this buffer
        if (t == 0) {
            int cn = c + NBUF * G;
            if (cn < nchunks) {
                fence_proxy();
                mbar_expect_tx(mbar_u32 + 8u * buf, CHUNK_BYTES);
                tma_1d(stage_u32 + (unsigned)buf * CHUNK_BYTES,
                       in4 + (size_t)cn * CHUNK_F4, CHUNK_BYTES, mbar_u32 + 8u * buf);
            }
        }
        ++local_i; c += G;
    }

    // ---- tails: float4 remainder, then scalar remainder -------------------
    for (int i = nchunks * CHUNK_F4 + blockIdx.x * THREADS + (int)t;
         i < n4; i += G * THREADS) {
        float4 v = __ldcs(in4 + i);
        DE3_BUMP4(v);
    }
    if (blockIdx.x == 0 && (int)t < (n & 3)) {
        float v = in[(n & ~3) + (int)t];
        DE3_BUMP(v);
    }
    #undef DE3_BUMP4
    #undef DE3_BUMP
    __syncthreads();

    // ---- block reduction (R7, proven): thread j sums bins j, j+128 --------
    const unsigned j = t;
    unsigned tot0 = 0u, tot1 = 0u;
    #pragma unroll
    for (int w = 0; w < 4; ++w) {
        const unsigned base0 = ((unsigned)w << 14) + j * 64u;
        const unsigned base1 = ((unsigned)w << 14) + (j + 128u) * 64u;
        unsigned acc0 = 0u, acc1 = 0u;
        #pragma unroll
        for (unsigned s = 0; s < 16; ++s) {
            unsigned k = (((j >> 1) + s) & 15u) << 2;
            acc0 += *reinterpret_cast<const unsigned*>(smem + base0 + k);
            acc1 += *reinterpret_cast<const unsigned*>(smem + base1 + k);
        }
        tot0 += (acc0 & 0xFFFFu) + (acc0 >> 16);
        tot1 += (acc1 & 0xFFFFu) + (acc1 >> 16);
    }
    atomicAdd(&g_counts[j],       tot0);
    atomicAdd(&g_counts[j + 128], tot1);

    // ---- last-block finalize ----------------------------------------------
    __threadfence();
    __shared__ unsigned ticket;
    if (t == 0) ticket = atomicAdd(&g_done, 1u);
    __syncthreads();

    if (ticket == gridDim.x - 1) {
        const float inv_temp = 1.0f / 4194304.0f;   // 1/(2048*2048)
        unsigned c0 = __ldcg(&g_counts[j]);
        unsigned c1 = __ldcg(&g_counts[j + 128]);
        double term = 0.0;
        if (c0) { float p = (float)c0 * inv_temp; term += (double)(p * log2f(p)); }
        if (c1) { float p = (float)c1 * inv_temp; term += (double)(p * log2f(p)); }

        #pragma unroll
        for (int o = 16; o > 0; o >>= 1)
            term += __shfl_down_sync(0xffffffffu, term, o);

        __shared__ double sred[4];
        if ((j & 31u) == 0u) sred[j >> 5] = term;
        __syncthreads();
        if (j == 0) {
            double s = sred[0] + sred[1] + sred[2] + sred[3];
            float B = (float)(n >> 22);              // n / (2048*2048)
            out[0] = (float)((double)B * (8.0 + s));
        }
        __syncthreads();
        // reset globals for the next graph replay
        g_counts[j] = 0u;
        g_counts[j + 128] = 0u;
        if (j == 0) g_done = 0u;
    }
}

extern "C" void kernel_launch(void* const* d_in, const int* in_sizes, int n_in,
                              void* d_out, int out_size) {
    const float* img = (const float*)d_in[0];
    int n = in_sizes[0];
    cudaFuncSetAttribute(de3_fused,
                         cudaFuncAttributeMaxDynamicSharedMemorySize, SMEM_BYTES);
    de3_fused<<<BLOCKS, THREADS, SMEM_BYTES>>>(
        (const float4*)img, n >> 2, img, n, (float*)d_out);
}